// round 2
// baseline (speedup 1.0000x reference)
#include <cuda_runtime.h>
#include <cstdint>

// Problem dims
#define NROWS 8192   // NUM_SENT * SENT_LEN
#define DD    512    // HIDDEN == OUT

// GEMM tile config
#define BM 128
#define BN 128
#define BK 16
#define AST 20    // A smem row stride (floats), pad 4 -> conflict-free frag loads
#define BST 136   // B smem row stride (floats), pad 8 -> conflict-free frag loads
#define NSTAGE 3
#define A_BUF (BM*AST)
#define B_BUF (BK*BST)
#define SMEM_BYTES (NSTAGE*(A_BUF+B_BUF)*4)

// Scratch (device globals: no allocations allowed)
__device__ float g_hud[NROWS*DD];
__device__ float g_hlr[NROWS*DD];
__device__ float g_Wt  [DD*DD];
__device__ float g_Wudt[DD*DD];
__device__ float g_Wlrt[DD*DD];
__device__ float g_Wgt [DD*DD];
__device__ float g_pooled[DD];
__device__ float g_nsum;
__device__ float g_biasT[DD];

// ---------------- helpers ----------------
__device__ __forceinline__ uint32_t smem_u32(const void* p){
    return (uint32_t)__cvta_generic_to_shared(p);
}
__device__ __forceinline__ void cpasync16(uint32_t s, const void* g){
    asm volatile("cp.async.cg.shared.global [%0], [%1], 16;\n" :: "r"(s), "l"(g));
}
__device__ __forceinline__ uint32_t cvt_tf32(float x){
    uint32_t r; asm("cvt.rna.tf32.f32 %0, %1;" : "=r"(r) : "f"(x)); return r;
}
__device__ __forceinline__ void mma_tf32(float* c,
    uint32_t a0,uint32_t a1,uint32_t a2,uint32_t a3, uint32_t b0,uint32_t b1){
    asm volatile(
      "mma.sync.aligned.m16n8k8.row.col.f32.tf32.tf32.f32 "
      "{%0,%1,%2,%3},{%4,%5,%6,%7},{%8,%9},{%0,%1,%2,%3};\n"
      : "+f"(c[0]),"+f"(c[1]),"+f"(c[2]),"+f"(c[3])
      : "r"(a0),"r"(a1),"r"(a2),"r"(a3),"r"(b0),"r"(b1));
}

// ---------------- shared GEMM mainloop ----------------
// C tile [BM x BN] per block, 256 threads, warp grid 2(m) x 4(n), warp tile 64x32.
// getA(kt,m,k) -> &A[rowBase+m][kt*BK+k]  (A row-major, 16B-chunk granular: k in {0,4,8,12})
// getB(kt,k,n) -> &B[kt*BK+k][colBase+n]  (B row-major [K,N], n multiple of 4)
template<class FA, class FB>
__device__ __forceinline__ void gemm_loop(float (&acc)[4][4][4], int nk,
                                          FA getA, FB getB, float* sm)
{
    float* As = sm;
    float* Bs = sm + NSTAGE*A_BUF;
    const int tid = threadIdx.x;
    const uint32_t aBase = smem_u32(As);
    const uint32_t bBase = smem_u32(Bs);

    auto prefetch = [&](int kt, int buf){
        #pragma unroll
        for(int r=0;r<2;r++){
            int idx=(tid + r*256)*4;
            int m=idx>>4, k=idx&15;
            cpasync16(aBase + (uint32_t)(buf*A_BUF + m*AST + k)*4u, getA(kt,m,k));
        }
        #pragma unroll
        for(int r=0;r<2;r++){
            int idx=(tid + r*256)*4;
            int k=idx>>7, n=idx&127;
            cpasync16(bBase + (uint32_t)(buf*B_BUF + k*BST + n)*4u, getB(kt,k,n));
        }
    };

    const int lane = tid & 31;
    const int warp = tid >> 5;
    const int wm = (warp>>2)*64;
    const int wn = (warp&3)*32;
    const int gq = lane>>2, tq = lane&3;

    prefetch(0,0);
    asm volatile("cp.async.commit_group;\n" ::: "memory");
    if(nk>1) prefetch(1,1);
    asm volatile("cp.async.commit_group;\n" ::: "memory");

    for(int kt=0; kt<nk; ++kt){
        if(kt+2<nk) prefetch(kt+2,(kt+2)%3);
        asm volatile("cp.async.commit_group;\n" ::: "memory");
        asm volatile("cp.async.wait_group 2;\n" ::: "memory");
        __syncthreads();
        const int buf = kt%3;
        const float* Ab = As + buf*A_BUF;
        const float* Bb = Bs + buf*B_BUF;
        #pragma unroll
        for(int kk=0;kk<2;kk++){
            const int k0 = kk*8 + tq;
            uint32_t af[4][4], bf[4][2];
            #pragma unroll
            for(int mt=0;mt<4;mt++){
                const float* p = Ab + (wm + mt*16 + gq)*AST + k0;
                af[mt][0]=cvt_tf32(p[0]);
                af[mt][2]=cvt_tf32(p[4]);
                af[mt][1]=cvt_tf32(p[8*AST]);
                af[mt][3]=cvt_tf32(p[8*AST+4]);
            }
            #pragma unroll
            for(int nt=0;nt<4;nt++){
                const float* p = Bb + k0*BST + wn + nt*8 + gq;
                bf[nt][0]=cvt_tf32(p[0]);
                bf[nt][1]=cvt_tf32(p[4*BST]);
            }
            #pragma unroll
            for(int mt=0;mt<4;mt++)
                #pragma unroll
                for(int nt=0;nt<4;nt++)
                    mma_tf32(acc[mt][nt], af[mt][0],af[mt][1],af[mt][2],af[mt][3],
                             bf[nt][0],bf[nt][1]);
        }
        __syncthreads();
    }
}

#define ZERO_ACC(acc) do{ _Pragma("unroll") for(int i_=0;i_<4;i_++) \
    _Pragma("unroll") for(int j_=0;j_<4;j_++) \
    _Pragma("unroll") for(int q_=0;q_<4;q_++) acc[i_][j_][q_]=0.f; }while(0)

// ---------------- kernels ----------------

// Transpose W, W_ud, W_lr, W_g (all [DD,DD] row-major [n][k]) into [k][n] scratch.
__global__ void transpose_kernel(const float* __restrict__ W,
                                 const float* __restrict__ Wud,
                                 const float* __restrict__ Wlr,
                                 const float* __restrict__ Wg){
    __shared__ float tile[32][33];
    const float* src; float* dst;
    switch(blockIdx.z){
        case 0: src=W;   dst=g_Wt;   break;
        case 1: src=Wud; dst=g_Wudt; break;
        case 2: src=Wlr; dst=g_Wlrt; break;
        default:src=Wg;  dst=g_Wgt;  break;
    }
    int x = blockIdx.x*32 + threadIdx.x;   // k in src
    int y = blockIdx.y*32 + threadIdx.y;   // n in src
    #pragma unroll
    for(int i=0;i<32;i+=8)
        tile[threadIdx.y+i][threadIdx.x] = src[(size_t)(y+i)*DD + x];
    __syncthreads();
    int xo = blockIdx.y*32 + threadIdx.x;  // n
    int yo = blockIdx.x*32 + threadIdx.y;  // k
    #pragma unroll
    for(int i=0;i<32;i+=8)
        dst[(size_t)(yo+i)*DD + xo] = tile[threadIdx.x][threadIdx.y+i];
}

// n = sum(mask); also zero the pooled accumulator (graph replays need re-init).
__global__ void masksum_kernel(const float* __restrict__ mask){
    __shared__ float red[512];
    float s=0.f;
    for(int i=threadIdx.x;i<NROWS;i+=512) s += mask[i];
    red[threadIdx.x]=s; __syncthreads();
    for(int st=256;st>0;st>>=1){
        if(threadIdx.x<st) red[threadIdx.x]+=red[threadIdx.x+st];
        __syncthreads();
    }
    if(threadIdx.x==0) g_nsum = red[0];
    g_pooled[threadIdx.x] = 0.f;
}

// pooled[c] = sum_r mask[r] * relu( (xf @ Wg^T)[r,c] + b_g[c] )
__global__ void __launch_bounds__(256,2) pool_gemm_kernel(
        const float* __restrict__ xf, const float* __restrict__ b_g,
        const float* __restrict__ mask){
    extern __shared__ float sm[];
    const int rowBase = blockIdx.y*BM, colBase = blockIdx.x*BN;
    float acc[4][4][4]; ZERO_ACC(acc);
    auto getA=[&](int kt,int m,int k){ return xf + (size_t)(rowBase+m)*DD + kt*BK + k; };
    auto getB=[&](int kt,int k,int n){ return g_Wgt + (size_t)(kt*BK+k)*DD + colBase + n; };
    gemm_loop(acc, DD/BK, getA, getB, sm);

    const int lane=threadIdx.x&31, warp=threadIdx.x>>5;
    const int wm=(warp>>2)*64, wn=(warp&3)*32, gq=lane>>2, tq=lane&3;
    float cs[4][2]; 
    #pragma unroll
    for(int nt=0;nt<4;nt++){ cs[nt][0]=0.f; cs[nt][1]=0.f; }
    #pragma unroll
    for(int mt=0;mt<4;mt++){
        int r0 = rowBase + wm + mt*16 + gq;
        float m0 = mask[r0], m8 = mask[r0+8];
        #pragma unroll
        for(int nt=0;nt<4;nt++){
            int c0 = colBase + wn + nt*8 + 2*tq;
            float bg0 = b_g[c0], bg1 = b_g[c0+1];
            cs[nt][0] += fmaxf(acc[mt][nt][0]+bg0,0.f)*m0 + fmaxf(acc[mt][nt][2]+bg0,0.f)*m8;
            cs[nt][1] += fmaxf(acc[mt][nt][1]+bg1,0.f)*m0 + fmaxf(acc[mt][nt][3]+bg1,0.f)*m8;
        }
    }
    #pragma unroll
    for(int nt=0;nt<4;nt++){
        #pragma unroll
        for(int j=0;j<2;j++){
            float v = cs[nt][j];
            v += __shfl_xor_sync(0xffffffffu, v, 4);
            v += __shfl_xor_sync(0xffffffffu, v, 8);
            v += __shfl_xor_sync(0xffffffffu, v, 16);
            if(lane < 4){
                int c0 = colBase + wn + nt*8 + 2*tq + j;
                atomicAdd(&g_pooled[c0], v);
            }
        }
    }
}

// biasT[o] = b+b_ud+b_lr+b_go + (pooled/n) @ W_go^T ; also emit h_g to output tail.
__global__ void gobias_kernel(const float* __restrict__ W_go,
                              const float* __restrict__ b,
                              const float* __restrict__ b_ud,
                              const float* __restrict__ b_lr,
                              const float* __restrict__ b_go,
                              float* __restrict__ out_hg){
    __shared__ float hg[DD];
    float inv = 1.0f / g_nsum;
    for(int i=threadIdx.x;i<DD;i+=32) hg[i] = g_pooled[i]*inv;
    __syncthreads();
    int o = blockIdx.x*32 + threadIdx.x;
    const float4* w = (const float4*)(W_go + (size_t)o*DD);
    float s=0.f;
    #pragma unroll 4
    for(int j=0;j<DD/4;j++){
        float4 wv = w[j];
        s += hg[4*j+0]*wv.x + hg[4*j+1]*wv.y + hg[4*j+2]*wv.z + hg[4*j+3]*wv.w;
    }
    g_biasT[o] = s + b[o] + b_ud[o] + b_lr[o] + b_go[o];
    out_hg[o]  = hg[o];
}

// Big aggregation: h_ud = a_ud @ xf (z=0), h_lr = a_lr @ xf (z=1).
__global__ void __launch_bounds__(256,2) big_gemm_kernel(
        const float* __restrict__ a_ud, const float* __restrict__ a_lr,
        const float* __restrict__ xf){
    extern __shared__ float sm[];
    const float* A = blockIdx.z ? a_lr : a_ud;
    float* C       = blockIdx.z ? g_hlr : g_hud;
    const int rowBase = blockIdx.y*BM, colBase = blockIdx.x*BN;
    float acc[4][4][4]; ZERO_ACC(acc);
    auto getA=[&](int kt,int m,int k){ return A + (size_t)(rowBase+m)*NROWS + kt*BK + k; };
    auto getB=[&](int kt,int k,int n){ return xf + (size_t)(kt*BK+k)*DD + colBase + n; };
    gemm_loop(acc, NROWS/BK, getA, getB, sm);

    const int lane=threadIdx.x&31, warp=threadIdx.x>>5;
    const int wm=(warp>>2)*64, wn=(warp&3)*32, gq=lane>>2, tq=lane&3;
    #pragma unroll
    for(int mt=0;mt<4;mt++){
        int r0 = rowBase + wm + mt*16 + gq;
        #pragma unroll
        for(int nt=0;nt<4;nt++){
            int c0 = colBase + wn + nt*8 + 2*tq;
            *(float2*)(C + (size_t)r0*DD + c0)     = make_float2(acc[mt][nt][0], acc[mt][nt][1]);
            *(float2*)(C + (size_t)(r0+8)*DD + c0) = make_float2(acc[mt][nt][2], acc[mt][nt][3]);
        }
    }
}

// Final fused: h = relu( xf@W^T + h_ud@W_ud^T + h_lr@W_lr^T + biasT ), K=1536 in 3 segments.
__global__ void __launch_bounds__(256,2) final_gemm_kernel(
        const float* __restrict__ xf, float* __restrict__ out){
    extern __shared__ float sm[];
    const int rowBase = blockIdx.y*BM, colBase = blockIdx.x*BN;
    float acc[4][4][4]; ZERO_ACC(acc);
    auto getA=[&](int kt,int m,int k){
        int s = kt>>5; int kc = (kt&31)*BK + k;
        const float* A = (s==0)? xf : (s==1? (const float*)g_hud : (const float*)g_hlr);
        return A + (size_t)(rowBase+m)*DD + kc;
    };
    auto getB=[&](int kt,int k,int n){
        int s = kt>>5; int kc = (kt&31)*BK + k;
        const float* B = (s==0)? (const float*)g_Wt : (s==1? (const float*)g_Wudt : (const float*)g_Wlrt);
        return B + (size_t)kc*DD + colBase + n;
    };
    gemm_loop(acc, 96, getA, getB, sm);

    const int lane=threadIdx.x&31, warp=threadIdx.x>>5;
    const int wm=(warp>>2)*64, wn=(warp&3)*32, gq=lane>>2, tq=lane&3;
    #pragma unroll
    for(int mt=0;mt<4;mt++){
        int r0 = rowBase + wm + mt*16 + gq;
        #pragma unroll
        for(int nt=0;nt<4;nt++){
            int c0 = colBase + wn + nt*8 + 2*tq;
            float bb0 = g_biasT[c0], bb1 = g_biasT[c0+1];
            float2 v0 = make_float2(fmaxf(acc[mt][nt][0]+bb0,0.f), fmaxf(acc[mt][nt][1]+bb1,0.f));
            float2 v2 = make_float2(fmaxf(acc[mt][nt][2]+bb0,0.f), fmaxf(acc[mt][nt][3]+bb1,0.f));
            *(float2*)(out + (size_t)r0*DD + c0)     = v0;
            *(float2*)(out + (size_t)(r0+8)*DD + c0) = v2;
        }
    }
}

// ---------------- launch ----------------
extern "C" void kernel_launch(void* const* d_in, const int* in_sizes, int n_in,
                              void* d_out, int out_size){
    const float* x    = (const float*)d_in[0];
    const float* mask = (const float*)d_in[1];
    const float* a_ud = (const float*)d_in[2];
    const float* a_lr = (const float*)d_in[3];
    const float* W    = (const float*)d_in[4];
    const float* b    = (const float*)d_in[5];
    const float* W_ud = (const float*)d_in[6];
    const float* b_ud = (const float*)d_in[7];
    const float* W_lr = (const float*)d_in[8];
    const float* b_lr = (const float*)d_in[9];
    const float* W_g  = (const float*)d_in[10];
    const float* b_g  = (const float*)d_in[11];
    const float* W_go = (const float*)d_in[12];
    const float* b_go = (const float*)d_in[13];
    float* out = (float*)d_out;

    cudaFuncSetAttribute(pool_gemm_kernel,  cudaFuncAttributeMaxDynamicSharedMemorySize, SMEM_BYTES);
    cudaFuncSetAttribute(big_gemm_kernel,   cudaFuncAttributeMaxDynamicSharedMemorySize, SMEM_BYTES);
    cudaFuncSetAttribute(final_gemm_kernel, cudaFuncAttributeMaxDynamicSharedMemorySize, SMEM_BYTES);

    transpose_kernel<<<dim3(DD/32, DD/32, 4), dim3(32,8)>>>(W, W_ud, W_lr, W_g);
    masksum_kernel<<<1,512>>>(mask);
    pool_gemm_kernel<<<dim3(DD/BN, NROWS/BM), 256, SMEM_BYTES>>>(x, b_g, mask);
    gobias_kernel<<<DD/32, 32>>>(W_go, b, b_ud, b_lr, b_go, out + (size_t)NROWS*DD);
    big_gemm_kernel<<<dim3(DD/BN, NROWS/BM, 2), 256, SMEM_BYTES>>>(a_ud, a_lr, x);
    final_gemm_kernel<<<dim3(DD/BN, NROWS/BM), 256, SMEM_BYTES>>>(x, out);
}

// round 4
// speedup vs baseline: 1.7506x; 1.7506x over previous
#include <cuda_runtime.h>
#include <cuda_fp16.h>
#include <cstdint>

#define NROWS 8192
#define DD    512

// GEMM tile: BM=128, BN=128, BK=32, 256 threads, warp grid 2(m) x 4(n), warp tile 64x32
#define BM 128
#define BN 128
#define BK 32
#define ASTRIDE 80                 // bytes per A smem row (32 halves + 8 pad)
#define BSTRIDE 528                // bytes per B smem pair-row (128 half2 + 4 pad)
#define A_TILE (BM*ASTRIDE)        // 10240
#define B_TILE ((BK/2)*BSTRIDE)    // 8448
#define STAGE  (A_TILE + B_TILE)   // 18688
#define NSTAGE 3
#define SMEM_TOTAL (NSTAGE*STAGE)  // 56064

// ---------------- device scratch (no allocations allowed) ----------------
__device__ __half  g_xfH[NROWS*DD];          // xf fp16 row-major
__device__ __half2 g_xfP[(NROWS/2)*DD];      // xf k-pair-packed: [k/2][n]
__device__ __half  g_hud[NROWS*DD];          // a_ud @ xf, fp16
__device__ __half  g_hlr[NROWS*DD];          // a_lr @ xf, fp16
__device__ __half2 g_WP  [(DD/2)*DD];        // W^T pair-packed [k/2][n]
__device__ __half2 g_WudP[(DD/2)*DD];
__device__ __half2 g_WlrP[(DD/2)*DD];
__device__ __half2 g_WgP [(DD/2)*DD];
__device__ float   g_pooled[DD];
__device__ float   g_nsum;
__device__ float   g_biasT[DD];

// ---------------- helpers ----------------
__device__ __forceinline__ uint32_t smem_u32(const void* p){
    return (uint32_t)__cvta_generic_to_shared(p);
}
__device__ __forceinline__ void cpasync16(uint32_t s, const void* g){
    asm volatile("cp.async.cg.shared.global [%0], [%1], 16;\n" :: "r"(s), "l"(g));
}
__device__ __forceinline__ void hmma(float* c, const uint32_t a[4], const uint32_t b[2]){
    asm volatile(
      "mma.sync.aligned.m16n8k16.row.col.f32.f16.f16.f32 "
      "{%0,%1,%2,%3},{%4,%5,%6,%7},{%8,%9},{%0,%1,%2,%3};\n"
      : "+f"(c[0]),"+f"(c[1]),"+f"(c[2]),"+f"(c[3])
      : "r"(a[0]),"r"(a[1]),"r"(a[2]),"r"(a[3]),"r"(b[0]),"r"(b[1]));
}

#define ZERO_ACC(acc) do{ _Pragma("unroll") for(int i_=0;i_<4;i_++) \
    _Pragma("unroll") for(int j_=0;j_<4;j_++) \
    _Pragma("unroll") for(int q_=0;q_<4;q_++) acc[i_][j_][q_]=0.f; }while(0)

// One BK=32 tile of MMAs (two k16 steps). All LDS verified conflict-free.
__device__ __forceinline__ void compute_tile(const char* As, const char* Bs,
                                             float (&acc)[4][4][4],
                                             int wm,int wn,int gq,int tq){
    #pragma unroll
    for(int kk=0;kk<2;kk++){
        const int k0 = kk*16;
        uint32_t a[4][4], b[4][2];
        #pragma unroll
        for(int mt=0;mt<4;mt++){
            const char* p = As + (wm + mt*16 + gq)*ASTRIDE + (k0 + 2*tq)*2;
            a[mt][0] = *(const uint32_t*)(p);
            a[mt][1] = *(const uint32_t*)(p + 8*ASTRIDE);
            a[mt][2] = *(const uint32_t*)(p + 16);
            a[mt][3] = *(const uint32_t*)(p + 8*ASTRIDE + 16);
        }
        #pragma unroll
        for(int nt=0;nt<4;nt++){
            const char* p = Bs + (k0/2 + tq)*BSTRIDE + (wn + nt*8 + gq)*4;
            b[nt][0] = *(const uint32_t*)(p);
            b[nt][1] = *(const uint32_t*)(p + 4*BSTRIDE);
        }
        #pragma unroll
        for(int mt=0;mt<4;mt++)
            #pragma unroll
            for(int nt=0;nt<4;nt++)
                hmma(acc[mt][nt], a[mt], b[nt]);
    }
}

// ---- mainloop A: A fp32 global, converted in-flight (big aggregations) ----
// getAf4(s, idx): idx in [0,1024): m=idx>>3, float4-chunk c=idx&7 of the BK=32 slice.
// getB16(s, idx): idx in [0,512): pair-row p=idx>>5, 16B chunk c=idx&31.
template<class FA, class FB>
__device__ __forceinline__ void mainloop_conv(int nk, float (&acc)[4][4][4],
                                              char* sm, FA getAf4, FB getB16){
    const int tid = threadIdx.x;
    const uint32_t smb = smem_u32(sm);
    const int lane=tid&31, warp=tid>>5;
    const int wm=(warp>>2)*64, wn=(warp&3)*32, gq=lane>>2, tq=lane&3;

    float4 av[4];
    #pragma unroll
    for(int r=0;r<4;r++) av[r] = __ldg(getAf4(0, tid + r*256));

    // prologue: commit B(0), B(1)
    #pragma unroll
    for(int pg=0; pg<2; pg++){
        if(pg < nk){
            const uint32_t bb = smb + pg*STAGE + A_TILE;
            #pragma unroll
            for(int r=0;r<2;r++){
                int idx = tid + r*256; int p=idx>>5, c=idx&31;
                cpasync16(bb + p*BSTRIDE + c*16, getB16(pg, idx));
            }
        }
        asm volatile("cp.async.commit_group;" ::: "memory");
    }

    for(int kt=0; kt<nk; ++kt){
        const int buf = kt % NSTAGE;
        char* Ab = sm + buf*STAGE;
        char* Bb = Ab + A_TILE;
        // STS A(kt), converting fp32->fp16
        #pragma unroll
        for(int r=0;r<4;r++){
            int idx = tid + r*256; int m=idx>>3, c=idx&7;
            __half2 h0 = __floats2half2_rn(av[r].x, av[r].y);
            __half2 h1 = __floats2half2_rn(av[r].z, av[r].w);
            uint2 u; u.x = *(uint32_t*)&h0; u.y = *(uint32_t*)&h1;
            *(uint2*)(Ab + m*ASTRIDE + c*8) = u;
        }
        // prefetch next A into regs
        if(kt+1 < nk){
            #pragma unroll
            for(int r=0;r<4;r++) av[r] = __ldg(getAf4(kt+1, tid + r*256));
        }
        // cp.async B(kt+2)
        if(kt+2 < nk){
            const int nb = (kt+2) % NSTAGE;
            const uint32_t bb = smb + nb*STAGE + A_TILE;
            #pragma unroll
            for(int r=0;r<2;r++){
                int idx = tid + r*256; int p=idx>>5, c=idx&31;
                cpasync16(bb + p*BSTRIDE + c*16, getB16(kt+2, idx));
            }
        }
        asm volatile("cp.async.commit_group;" ::: "memory");
        asm volatile("cp.async.wait_group 2;" ::: "memory");
        __syncthreads();
        compute_tile(Ab, Bb, acc, wm, wn, gq, tq);
        __syncthreads();
    }
}

// ---- mainloop B: A fp16 global, both operands via cp.async (final/pool) ----
// getA16(s, idx): idx in [0,512): m=idx>>2, 16B chunk c=idx&3.
template<class FA, class FB>
__device__ __forceinline__ void mainloop_cp(int nk, float (&acc)[4][4][4],
                                            char* sm, FA getA16, FB getB16){
    const int tid = threadIdx.x;
    const uint32_t smb = smem_u32(sm);
    const int lane=tid&31, warp=tid>>5;
    const int wm=(warp>>2)*64, wn=(warp&3)*32, gq=lane>>2, tq=lane&3;

    auto stage_loads = [&](int s){
        const int buf = s % NSTAGE;
        const uint32_t ab = smb + buf*STAGE;
        const uint32_t bb = ab + A_TILE;
        #pragma unroll
        for(int r=0;r<2;r++){
            int idx = tid + r*256; int m=idx>>2, c=idx&3;
            cpasync16(ab + m*ASTRIDE + c*16, getA16(s, idx));
        }
        #pragma unroll
        for(int r=0;r<2;r++){
            int idx = tid + r*256; int p=idx>>5, c=idx&31;
            cpasync16(bb + p*BSTRIDE + c*16, getB16(s, idx));
        }
    };

    #pragma unroll
    for(int pg=0; pg<2; pg++){
        if(pg < nk) stage_loads(pg);
        asm volatile("cp.async.commit_group;" ::: "memory");
    }
    for(int kt=0; kt<nk; ++kt){
        if(kt+2 < nk) stage_loads(kt+2);
        asm volatile("cp.async.commit_group;" ::: "memory");
        asm volatile("cp.async.wait_group 2;" ::: "memory");
        __syncthreads();
        const int buf = kt % NSTAGE;
        compute_tile(sm + buf*STAGE, sm + buf*STAGE + A_TILE, acc, wm, wn, gq, tq);
        __syncthreads();
    }
}

// ---------------- prep kernels ----------------
// Pack weights: WP[k/2][n] = half2(W[n][2k'], W[n][2k'+1]) for 4 matrices.
__global__ void wpack_kernel(const float* __restrict__ W, const float* __restrict__ Wud,
                             const float* __restrict__ Wlr, const float* __restrict__ Wg){
    const float* src; __half2* dst;
    switch(blockIdx.z){
        case 0: src=W;   dst=g_WP;   break;
        case 1: src=Wud; dst=g_WudP; break;
        case 2: src=Wlr; dst=g_WlrP; break;
        default:src=Wg;  dst=g_WgP;  break;
    }
    int idx = blockIdx.x*256 + threadIdx.x;   // 131072 total
    int p = idx >> 9, n = idx & 511;
    float2 v = *(const float2*)(src + (size_t)n*DD + 2*p);
    dst[(size_t)p*DD + n] = __floats2half2_rn(v.x, v.y);
}

// xf -> fp16 row-major + k-pair-packed.
__global__ void xfconv_kernel(const float* __restrict__ xf){
    int idx = blockIdx.x*256 + threadIdx.x;   // 524288 total
    int p = idx >> 7, n4 = (idx & 127)*4;
    float4 v0 = *(const float4*)(xf + (size_t)(2*p)*DD + n4);
    float4 v1 = *(const float4*)(xf + (size_t)(2*p+1)*DD + n4);
    __half2 r0 = __floats2half2_rn(v0.x, v0.y), r1 = __floats2half2_rn(v0.z, v0.w);
    __half2 r2 = __floats2half2_rn(v1.x, v1.y), r3 = __floats2half2_rn(v1.z, v1.w);
    uint2 u0; u0.x=*(uint32_t*)&r0; u0.y=*(uint32_t*)&r1;
    uint2 u1; u1.x=*(uint32_t*)&r2; u1.y=*(uint32_t*)&r3;
    *(uint2*)(g_xfH + (size_t)(2*p)*DD + n4)   = u0;
    *(uint2*)(g_xfH + (size_t)(2*p+1)*DD + n4) = u1;
    __half2 p0 = __floats2half2_rn(v0.x, v1.x);
    __half2 p1 = __floats2half2_rn(v0.y, v1.y);
    __half2 p2 = __floats2half2_rn(v0.z, v1.z);
    __half2 p3 = __floats2half2_rn(v0.w, v1.w);
    uint4 up; up.x=*(uint32_t*)&p0; up.y=*(uint32_t*)&p1; up.z=*(uint32_t*)&p2; up.w=*(uint32_t*)&p3;
    *(uint4*)(g_xfP + (size_t)p*DD + n4) = up;
}

__global__ void masksum_kernel(const float* __restrict__ mask){
    __shared__ float red[512];
    float s=0.f;
    for(int i=threadIdx.x;i<NROWS;i+=512) s += mask[i];
    red[threadIdx.x]=s; __syncthreads();
    for(int st=256;st>0;st>>=1){
        if(threadIdx.x<st) red[threadIdx.x]+=red[threadIdx.x+st];
        __syncthreads();
    }
    if(threadIdx.x==0) g_nsum = red[0];
    g_pooled[threadIdx.x] = 0.f;
}

__global__ void gobias_kernel(const float* __restrict__ W_go,
                              const float* __restrict__ b,  const float* __restrict__ b_ud,
                              const float* __restrict__ b_lr,const float* __restrict__ b_go,
                              float* __restrict__ out_hg){
    __shared__ float hg[DD];
    float inv = 1.0f / g_nsum;
    for(int i=threadIdx.x;i<DD;i+=256) hg[i] = g_pooled[i]*inv;
    __syncthreads();
    int warp = threadIdx.x>>5, lane = threadIdx.x&31;
    int o = blockIdx.x*8 + warp;
    const float4* wr = (const float4*)(W_go + (size_t)o*DD);
    float s=0.f;
    #pragma unroll
    for(int j=lane;j<DD/4;j+=32){
        float4 wv = wr[j];
        s += hg[4*j]*wv.x + hg[4*j+1]*wv.y + hg[4*j+2]*wv.z + hg[4*j+3]*wv.w;
    }
    #pragma unroll
    for(int st=16;st>0;st>>=1) s += __shfl_xor_sync(0xffffffffu, s, st);
    if(lane==0) g_biasT[o] = s + b[o] + b_ud[o] + b_lr[o] + b_go[o];
    if(blockIdx.x==0)
        for(int i=threadIdx.x;i<DD;i+=256) out_hg[i] = hg[i];
}

// ---------------- GEMM kernels ----------------

// h_ud = a_ud @ xf (z=0), h_lr = a_lr @ xf (z=1); A fp32 converted in-flight; out fp16.
__global__ void __launch_bounds__(256,2) big_gemm_kernel(
        const float* __restrict__ a_ud, const float* __restrict__ a_lr){
    extern __shared__ char sm[];
    const float* A = blockIdx.z ? a_lr : a_ud;
    __half* C      = blockIdx.z ? g_hlr : g_hud;
    const size_t rowBase = (size_t)blockIdx.y * BM;
    const int colBase = blockIdx.x * BN;
    float acc[4][4][4]; ZERO_ACC(acc);
    auto getAf4=[&](int s,int idx){
        int m=idx>>3, c=idx&7;
        return (const float4*)(A + (rowBase+m)*NROWS + s*BK + c*4);
    };
    auto getB16=[&](int s,int idx){
        int p=idx>>5, c=idx&31;
        return (const void*)(g_xfP + (size_t)(s*16+p)*DD + colBase + c*4);
    };
    mainloop_conv(NROWS/BK, acc, sm, getAf4, getB16);

    const int lane=threadIdx.x&31, warp=threadIdx.x>>5;
    const int wm=(warp>>2)*64, wn=(warp&3)*32, gq=lane>>2, tq=lane&3;
    #pragma unroll
    for(int mt=0;mt<4;mt++){
        size_t r0 = rowBase + wm + mt*16 + gq;
        #pragma unroll
        for(int nt=0;nt<4;nt++){
            int c0 = colBase + wn + nt*8 + 2*tq;
            *(__half2*)(C + r0*DD + c0)     = __floats2half2_rn(acc[mt][nt][0], acc[mt][nt][1]);
            *(__half2*)(C + (r0+8)*DD + c0) = __floats2half2_rn(acc[mt][nt][2], acc[mt][nt][3]);
        }
    }
}

// pooled[c] += sum_r mask[r]*relu((xf@Wg^T)[r,c] + b_g[c])
__global__ void __launch_bounds__(256,2) pool_gemm_kernel(
        const float* __restrict__ b_g, const float* __restrict__ mask){
    extern __shared__ char sm[];
    const size_t rowBase = (size_t)blockIdx.y * BM;
    const int colBase = blockIdx.x * BN;
    float acc[4][4][4]; ZERO_ACC(acc);
    auto getA16=[&](int s,int idx){
        int m=idx>>2, c=idx&3;
        return (const void*)(g_xfH + (rowBase+m)*DD + s*BK + c*8);
    };
    auto getB16=[&](int s,int idx){
        int p=idx>>5, c=idx&31;
        return (const void*)(g_WgP + (size_t)(s*16+p)*DD + colBase + c*4);
    };
    mainloop_cp(DD/BK, acc, sm, getA16, getB16);

    const int lane=threadIdx.x&31, warp=threadIdx.x>>5;
    const int wm=(warp>>2)*64, wn=(warp&3)*32, gq=lane>>2, tq=lane&3;
    float cs[4][2];
    #pragma unroll
    for(int nt=0;nt<4;nt++){ cs[nt][0]=0.f; cs[nt][1]=0.f; }
    #pragma unroll
    for(int mt=0;mt<4;mt++){
        size_t r0 = rowBase + wm + mt*16 + gq;
        float m0 = mask[r0], m8 = mask[r0+8];
        #pragma unroll
        for(int nt=0;nt<4;nt++){
            int c0 = colBase + wn + nt*8 + 2*tq;
            float bg0 = b_g[c0], bg1 = b_g[c0+1];
            cs[nt][0] += fmaxf(acc[mt][nt][0]+bg0,0.f)*m0 + fmaxf(acc[mt][nt][2]+bg0,0.f)*m8;
            cs[nt][1] += fmaxf(acc[mt][nt][1]+bg1,0.f)*m0 + fmaxf(acc[mt][nt][3]+bg1,0.f)*m8;
        }
    }
    #pragma unroll
    for(int nt=0;nt<4;nt++){
        #pragma unroll
        for(int j=0;j<2;j++){
            float v = cs[nt][j];
            v += __shfl_xor_sync(0xffffffffu, v, 4);
            v += __shfl_xor_sync(0xffffffffu, v, 8);
            v += __shfl_xor_sync(0xffffffffu, v, 16);
            if(lane < 4){
                int c0 = colBase + wn + nt*8 + 2*tq + j;
                atomicAdd(&g_pooled[c0], v);
            }
        }
    }
}

// h = relu( xf@W^T + h_ud@W_ud^T + h_lr@W_lr^T + biasT ), K=1536 in 3 fp16 segments.
__global__ void __launch_bounds__(256,2) final_gemm_kernel(float* __restrict__ out){
    extern __shared__ char sm[];
    const size_t rowBase = (size_t)blockIdx.y * BM;
    const int colBase = blockIdx.x * BN;
    float acc[4][4][4]; ZERO_ACC(acc);
    auto getA16=[&](int s,int idx){
        int m=idx>>2, c=idx&3;
        int seg=s>>4; int ks=(s&15)*BK + c*8;
        const __half* Ah = seg==0 ? g_xfH : (seg==1 ? g_hud : g_hlr);
        return (const void*)(Ah + (rowBase+m)*DD + ks);
    };
    auto getB16=[&](int s,int idx){
        int p=idx>>5, c=idx&31;
        int seg=s>>4; int gp=(s&15)*16 + p;
        const __half2* Bp = seg==0 ? g_WP : (seg==1 ? g_WudP : g_WlrP);
        return (const void*)(Bp + (size_t)gp*DD + colBase + c*4);
    };
    mainloop_cp(3*DD/BK, acc, sm, getA16, getB16);

    const int lane=threadIdx.x&31, warp=threadIdx.x>>5;
    const int wm=(warp>>2)*64, wn=(warp&3)*32, gq=lane>>2, tq=lane&3;
    #pragma unroll
    for(int mt=0;mt<4;mt++){
        size_t r0 = rowBase + wm + mt*16 + gq;
        #pragma unroll
        for(int nt=0;nt<4;nt++){
            int c0 = colBase + wn + nt*8 + 2*tq;
            float bb0 = g_biasT[c0], bb1 = g_biasT[c0+1];
            float2 v0 = make_float2(fmaxf(acc[mt][nt][0]+bb0,0.f), fmaxf(acc[mt][nt][1]+bb1,0.f));
            float2 v2 = make_float2(fmaxf(acc[mt][nt][2]+bb0,0.f), fmaxf(acc[mt][nt][3]+bb1,0.f));
            *(float2*)(out + r0*DD + c0)     = v0;
            *(float2*)(out + (r0+8)*DD + c0) = v2;
        }
    }
}

// ---------------- launch ----------------
extern "C" void kernel_launch(void* const* d_in, const int* in_sizes, int n_in,
                              void* d_out, int out_size){
    const float* x    = (const float*)d_in[0];
    const float* mask = (const float*)d_in[1];
    const float* a_ud = (const float*)d_in[2];
    const float* a_lr = (const float*)d_in[3];
    const float* W    = (const float*)d_in[4];
    const float* b    = (const float*)d_in[5];
    const float* W_ud = (const float*)d_in[6];
    const float* b_ud = (const float*)d_in[7];
    const float* W_lr = (const float*)d_in[8];
    const float* b_lr = (const float*)d_in[9];
    const float* W_g  = (const float*)d_in[10];
    const float* b_g  = (const float*)d_in[11];
    const float* W_go = (const float*)d_in[12];
    const float* b_go = (const float*)d_in[13];
    float* out = (float*)d_out;

    static bool attr_done = false;
    if(!attr_done){
        cudaFuncSetAttribute(big_gemm_kernel,   cudaFuncAttributeMaxDynamicSharedMemorySize, SMEM_TOTAL);
        cudaFuncSetAttribute(pool_gemm_kernel,  cudaFuncAttributeMaxDynamicSharedMemorySize, SMEM_TOTAL);
        cudaFuncSetAttribute(final_gemm_kernel, cudaFuncAttributeMaxDynamicSharedMemorySize, SMEM_TOTAL);
        attr_done = true;
    }

    wpack_kernel<<<dim3(512,1,4), 256>>>(W, W_ud, W_lr, W_g);
    xfconv_kernel<<<2048, 256>>>(x);
    masksum_kernel<<<1,512>>>(mask);
    pool_gemm_kernel<<<dim3(DD/BN, NROWS/BM), 256, SMEM_TOTAL>>>(b_g, mask);
    gobias_kernel<<<DD/8, 256>>>(W_go, b, b_ud, b_lr, b_go, out + (size_t)NROWS*DD);
    big_gemm_kernel<<<dim3(DD/BN, NROWS/BM, 2), 256, SMEM_TOTAL>>>(a_ud, a_lr);
    final_gemm_kernel<<<dim3(DD/BN, NROWS/BM), 256, SMEM_TOTAL>>>(out);
}

// round 5
// speedup vs baseline: 2.2665x; 1.2947x over previous
#include <cuda_runtime.h>
#include <cuda_fp16.h>
#include <cstdint>

#define NROWS 8192
#define DD    512

// GEMM tile: BM=128, BN=128, BK=32, 256 threads, warp grid 2(m) x 4(n), warp tile 64x32
#define BM 128
#define BN 128
#define BK 32
#define ASTRIDE 80                 // bytes per A smem row (32 halves + pad); LDSM conflict-free
#define BSTRIDE 544                // bytes per B smem pair-row; 544/4 % 32 == 8 -> conflict-free
#define A_TILE (BM*ASTRIDE)        // 10240
#define B_TILE ((BK/2)*BSTRIDE)    // 8704
#define STAGE  (A_TILE + B_TILE)   // 18944
#define NSTAGE 4
#define SMEM_TOTAL (NSTAGE*STAGE)  // 75776 (2 CTAs/SM: 151552 <= 227KB)

// ---------------- device scratch (no allocations allowed) ----------------
__device__ __half  g_xfH[NROWS*DD];          // xf fp16 row-major
__device__ __half2 g_xfP[(NROWS/2)*DD];      // xf k-pair-packed: [k/2][n]
__device__ __half  g_hud[NROWS*DD];          // a_ud @ xf, fp16
__device__ __half  g_hlr[NROWS*DD];          // a_lr @ xf, fp16
__device__ __half2 g_WP  [(DD/2)*DD];        // W^T pair-packed [k/2][n]
__device__ __half2 g_WudP[(DD/2)*DD];
__device__ __half2 g_WlrP[(DD/2)*DD];
__device__ __half2 g_WgP [(DD/2)*DD];
__device__ float   g_pooled[DD];
__device__ float   g_nsum;
__device__ float   g_biasT[DD];

// ---------------- helpers ----------------
__device__ __forceinline__ uint32_t smem_u32(const void* p){
    return (uint32_t)__cvta_generic_to_shared(p);
}
__device__ __forceinline__ void cpasync16(uint32_t s, const void* g){
    asm volatile("cp.async.cg.shared.global [%0], [%1], 16;\n" :: "r"(s), "l"(g));
}
__device__ __forceinline__ void hmma(float* c, const uint32_t a[4], const uint32_t b[2]){
    asm volatile(
      "mma.sync.aligned.m16n8k16.row.col.f32.f16.f16.f32 "
      "{%0,%1,%2,%3},{%4,%5,%6,%7},{%8,%9},{%0,%1,%2,%3};\n"
      : "+f"(c[0]),"+f"(c[1]),"+f"(c[2]),"+f"(c[3])
      : "r"(a[0]),"r"(a[1]),"r"(a[2]),"r"(a[3]),"r"(b[0]),"r"(b[1]));
}
__device__ __forceinline__ void ldsm4(uint32_t* r, uint32_t addr){
    asm volatile("ldmatrix.sync.aligned.m8n8.x4.shared.b16 {%0,%1,%2,%3}, [%4];"
        : "=r"(r[0]),"=r"(r[1]),"=r"(r[2]),"=r"(r[3]) : "r"(addr));
}
__device__ __forceinline__ uint32_t lds32(uint32_t addr){
    uint32_t v; asm volatile("ld.shared.b32 %0, [%1];" : "=r"(v) : "r"(addr)); return v;
}
__device__ __forceinline__ void sts_u2(uint32_t addr, uint32_t x, uint32_t y){
    asm volatile("st.shared.v2.b32 [%0], {%1,%2};" :: "r"(addr), "r"(x), "r"(y));
}

#define ZERO_ACC(acc) do{ _Pragma("unroll") for(int i_=0;i_<4;i_++) \
    _Pragma("unroll") for(int j_=0;j_<4;j_++) \
    _Pragma("unroll") for(int q_=0;q_<4;q_++) acc[i_][j_][q_]=0.f; }while(0)

// One BK=32 tile of MMAs (two k16 steps). A via ldmatrix.x4, B via LDS.32.
__device__ __forceinline__ void compute_tile(uint32_t As, uint32_t Bs,
                                             float (&acc)[4][4][4],
                                             int wm,int wn,int gq,int tq,int lane){
    const uint32_t arow = lane & 15;
    const uint32_t acol = (lane >> 4) * 16;          // bytes
    const uint32_t abase = As + (wm + arow)*ASTRIDE + acol;
    const uint32_t bbase = Bs + tq*BSTRIDE + (wn + gq)*4;
    #pragma unroll
    for(int kk=0;kk<2;kk++){
        uint32_t a[4][4], b[4][2];
        #pragma unroll
        for(int mt=0;mt<4;mt++)
            ldsm4(a[mt], abase + mt*16*ASTRIDE + kk*32);
        #pragma unroll
        for(int nt=0;nt<4;nt++){
            uint32_t p = bbase + kk*8*BSTRIDE + nt*32;
            b[nt][0] = lds32(p);
            b[nt][1] = lds32(p + 4*BSTRIDE);
        }
        #pragma unroll
        for(int mt=0;mt<4;mt++)
            #pragma unroll
            for(int nt=0;nt<4;nt++)
                hmma(acc[mt][nt], a[mt], b[nt]);
    }
}

// ---- mainloop A: A fp32 global, converted in-flight (big aggregations) ----
// 4-stage, write-distance 2, ONE syncthreads per iteration.
template<class FA, class FB>
__device__ __forceinline__ void mainloop_conv(int nk, float (&acc)[4][4][4],
                                              char* sm, FA getAf4, FB getB16){
    const int tid = threadIdx.x;
    const uint32_t smb = smem_u32(sm);
    const int lane=tid&31, warp=tid>>5;
    const int wm=(warp>>2)*64, wn=(warp&3)*32, gq=lane>>2, tq=lane&3;

    float4 av[4];
    #pragma unroll
    for(int r=0;r<4;r++) av[r] = __ldg(getAf4(0, tid + r*256));

    // prologue: commit B(0), B(1)
    #pragma unroll
    for(int pg=0; pg<2; pg++){
        if(pg < nk){
            const uint32_t bb = smb + pg*STAGE + A_TILE;
            #pragma unroll
            for(int r=0;r<2;r++){
                int idx = tid + r*256; int p=idx>>5, c=idx&31;
                cpasync16(bb + p*BSTRIDE + c*16, getB16(pg, idx));
            }
        }
        asm volatile("cp.async.commit_group;" ::: "memory");
    }

    for(int kt=0; kt<nk; ++kt){
        const int buf = kt & 3;
        const uint32_t ab = smb + buf*STAGE;
        // STS A(kt), converting fp32->fp16 (writes buf kt%4; only compute(kt) reads it)
        #pragma unroll
        for(int r=0;r<4;r++){
            int idx = tid + r*256; int m=idx>>3, c=idx&7;
            __half2 h0 = __floats2half2_rn(av[r].x, av[r].y);
            __half2 h1 = __floats2half2_rn(av[r].z, av[r].w);
            sts_u2(ab + m*ASTRIDE + c*8, *(uint32_t*)&h0, *(uint32_t*)&h1);
        }
        if(kt+1 < nk){
            #pragma unroll
            for(int r=0;r<4;r++) av[r] = __ldg(getAf4(kt+1, tid + r*256));
        }
        if(kt+2 < nk){
            const uint32_t bb = smb + ((kt+2)&3)*STAGE + A_TILE;
            #pragma unroll
            for(int r=0;r<2;r++){
                int idx = tid + r*256; int p=idx>>5, c=idx&31;
                cpasync16(bb + p*BSTRIDE + c*16, getB16(kt+2, idx));
            }
        }
        asm volatile("cp.async.commit_group;" ::: "memory");
        asm volatile("cp.async.wait_group 2;" ::: "memory");
        __syncthreads();
        compute_tile(ab, ab + A_TILE, acc, wm, wn, gq, tq, lane);
    }
}

// ---- mainloop B: both operands via cp.async (final/pool) ----
template<class FA, class FB>
__device__ __forceinline__ void mainloop_cp(int nk, float (&acc)[4][4][4],
                                            char* sm, FA getA16, FB getB16){
    const int tid = threadIdx.x;
    const uint32_t smb = smem_u32(sm);
    const int lane=tid&31, warp=tid>>5;
    const int wm=(warp>>2)*64, wn=(warp&3)*32, gq=lane>>2, tq=lane&3;

    auto stage_loads = [&](int s){
        const uint32_t ab = smb + (s&3)*STAGE;
        const uint32_t bb = ab + A_TILE;
        #pragma unroll
        for(int r=0;r<2;r++){
            int idx = tid + r*256; int m=idx>>2, c=idx&3;
            cpasync16(ab + m*ASTRIDE + c*16, getA16(s, idx));
        }
        #pragma unroll
        for(int r=0;r<2;r++){
            int idx = tid + r*256; int p=idx>>5, c=idx&31;
            cpasync16(bb + p*BSTRIDE + c*16, getB16(s, idx));
        }
    };

    #pragma unroll
    for(int pg=0; pg<2; pg++){
        if(pg < nk) stage_loads(pg);
        asm volatile("cp.async.commit_group;" ::: "memory");
    }
    for(int kt=0; kt<nk; ++kt){
        if(kt+2 < nk) stage_loads(kt+2);
        asm volatile("cp.async.commit_group;" ::: "memory");
        asm volatile("cp.async.wait_group 2;" ::: "memory");
        __syncthreads();
        const uint32_t ab = smb + (kt&3)*STAGE;
        compute_tile(ab, ab + A_TILE, acc, wm, wn, gq, tq, lane);
    }
}

// ---------------- prep kernels ----------------
__global__ void wpack_kernel(const float* __restrict__ W, const float* __restrict__ Wud,
                             const float* __restrict__ Wlr, const float* __restrict__ Wg){
    const float* src; __half2* dst;
    switch(blockIdx.z){
        case 0: src=W;   dst=g_WP;   break;
        case 1: src=Wud; dst=g_WudP; break;
        case 2: src=Wlr; dst=g_WlrP; break;
        default:src=Wg;  dst=g_WgP;  break;
    }
    int idx = blockIdx.x*256 + threadIdx.x;   // 131072 total
    int p = idx >> 9, n = idx & 511;
    float2 v = *(const float2*)(src + (size_t)n*DD + 2*p);
    dst[(size_t)p*DD + n] = __floats2half2_rn(v.x, v.y);
}

__global__ void xfconv_kernel(const float* __restrict__ xf){
    int idx = blockIdx.x*256 + threadIdx.x;   // 524288 total
    int p = idx >> 7, n4 = (idx & 127)*4;
    float4 v0 = *(const float4*)(xf + (size_t)(2*p)*DD + n4);
    float4 v1 = *(const float4*)(xf + (size_t)(2*p+1)*DD + n4);
    __half2 r0 = __floats2half2_rn(v0.x, v0.y), r1 = __floats2half2_rn(v0.z, v0.w);
    __half2 r2 = __floats2half2_rn(v1.x, v1.y), r3 = __floats2half2_rn(v1.z, v1.w);
    uint2 u0; u0.x=*(uint32_t*)&r0; u0.y=*(uint32_t*)&r1;
    uint2 u1; u1.x=*(uint32_t*)&r2; u1.y=*(uint32_t*)&r3;
    *(uint2*)(g_xfH + (size_t)(2*p)*DD + n4)   = u0;
    *(uint2*)(g_xfH + (size_t)(2*p+1)*DD + n4) = u1;
    __half2 p0 = __floats2half2_rn(v0.x, v1.x);
    __half2 p1 = __floats2half2_rn(v0.y, v1.y);
    __half2 p2 = __floats2half2_rn(v0.z, v1.z);
    __half2 p3 = __floats2half2_rn(v0.w, v1.w);
    uint4 up; up.x=*(uint32_t*)&p0; up.y=*(uint32_t*)&p1; up.z=*(uint32_t*)&p2; up.w=*(uint32_t*)&p3;
    *(uint4*)(g_xfP + (size_t)p*DD + n4) = up;
}

__global__ void masksum_kernel(const float* __restrict__ mask){
    __shared__ float red[512];
    float s=0.f;
    for(int i=threadIdx.x;i<NROWS;i+=512) s += mask[i];
    red[threadIdx.x]=s; __syncthreads();
    for(int st=256;st>0;st>>=1){
        if(threadIdx.x<st) red[threadIdx.x]+=red[threadIdx.x+st];
        __syncthreads();
    }
    if(threadIdx.x==0) g_nsum = red[0];
    g_pooled[threadIdx.x] = 0.f;
}

__global__ void gobias_kernel(const float* __restrict__ W_go,
                              const float* __restrict__ b,  const float* __restrict__ b_ud,
                              const float* __restrict__ b_lr,const float* __restrict__ b_go,
                              float* __restrict__ out_hg){
    __shared__ float hg[DD];
    float inv = 1.0f / g_nsum;
    for(int i=threadIdx.x;i<DD;i+=256) hg[i] = g_pooled[i]*inv;
    __syncthreads();
    int warp = threadIdx.x>>5, lane = threadIdx.x&31;
    int o = blockIdx.x*8 + warp;
    const float4* wr = (const float4*)(W_go + (size_t)o*DD);
    float s=0.f;
    #pragma unroll
    for(int j=lane;j<DD/4;j+=32){
        float4 wv = wr[j];
        s += hg[4*j]*wv.x + hg[4*j+1]*wv.y + hg[4*j+2]*wv.z + hg[4*j+3]*wv.w;
    }
    #pragma unroll
    for(int st=16;st>0;st>>=1) s += __shfl_xor_sync(0xffffffffu, s, st);
    if(lane==0) g_biasT[o] = s + b[o] + b_ud[o] + b_lr[o] + b_go[o];
    if(blockIdx.x==0)
        for(int i=threadIdx.x;i<DD;i+=256) out_hg[i] = hg[i];
}

// ---------------- GEMM kernels ----------------

__global__ void __launch_bounds__(256,2) big_gemm_kernel(
        const float* __restrict__ a_ud, const float* __restrict__ a_lr){
    extern __shared__ char sm[];
    const float* A = blockIdx.z ? a_lr : a_ud;
    __half* C      = blockIdx.z ? g_hlr : g_hud;
    const size_t rowBase = (size_t)blockIdx.y * BM;
    const int colBase = blockIdx.x * BN;
    float acc[4][4][4]; ZERO_ACC(acc);
    auto getAf4=[&](int s,int idx){
        int m=idx>>3, c=idx&7;
        return (const float4*)(A + (rowBase+m)*NROWS + s*BK + c*4);
    };
    auto getB16=[&](int s,int idx){
        int p=idx>>5, c=idx&31;
        return (const void*)(g_xfP + (size_t)(s*16+p)*DD + colBase + c*4);
    };
    mainloop_conv(NROWS/BK, acc, sm, getAf4, getB16);

    const int lane=threadIdx.x&31, warp=threadIdx.x>>5;
    const int wm=(warp>>2)*64, wn=(warp&3)*32, gq=lane>>2, tq=lane&3;
    #pragma unroll
    for(int mt=0;mt<4;mt++){
        size_t r0 = rowBase + wm + mt*16 + gq;
        #pragma unroll
        for(int nt=0;nt<4;nt++){
            int c0 = colBase + wn + nt*8 + 2*tq;
            *(__half2*)(C + r0*DD + c0)     = __floats2half2_rn(acc[mt][nt][0], acc[mt][nt][1]);
            *(__half2*)(C + (r0+8)*DD + c0) = __floats2half2_rn(acc[mt][nt][2], acc[mt][nt][3]);
        }
    }
}

__global__ void __launch_bounds__(256,2) pool_gemm_kernel(
        const float* __restrict__ b_g, const float* __restrict__ mask){
    extern __shared__ char sm[];
    const size_t rowBase = (size_t)blockIdx.y * BM;
    const int colBase = blockIdx.x * BN;
    float acc[4][4][4]; ZERO_ACC(acc);
    auto getA16=[&](int s,int idx){
        int m=idx>>2, c=idx&3;
        return (const void*)(g_xfH + (rowBase+m)*DD + s*BK + c*8);
    };
    auto getB16=[&](int s,int idx){
        int p=idx>>5, c=idx&31;
        return (const void*)(g_WgP + (size_t)(s*16+p)*DD + colBase + c*4);
    };
    mainloop_cp(DD/BK, acc, sm, getA16, getB16);

    const int lane=threadIdx.x&31, warp=threadIdx.x>>5;
    const int wm=(warp>>2)*64, wn=(warp&3)*32, gq=lane>>2, tq=lane&3;
    float cs[4][2];
    #pragma unroll
    for(int nt=0;nt<4;nt++){ cs[nt][0]=0.f; cs[nt][1]=0.f; }
    #pragma unroll
    for(int mt=0;mt<4;mt++){
        size_t r0 = rowBase + wm + mt*16 + gq;
        float m0 = mask[r0], m8 = mask[r0+8];
        #pragma unroll
        for(int nt=0;nt<4;nt++){
            int c0 = colBase + wn + nt*8 + 2*tq;
            float bg0 = b_g[c0], bg1 = b_g[c0+1];
            cs[nt][0] += fmaxf(acc[mt][nt][0]+bg0,0.f)*m0 + fmaxf(acc[mt][nt][2]+bg0,0.f)*m8;
            cs[nt][1] += fmaxf(acc[mt][nt][1]+bg1,0.f)*m0 + fmaxf(acc[mt][nt][3]+bg1,0.f)*m8;
        }
    }
    #pragma unroll
    for(int nt=0;nt<4;nt++){
        #pragma unroll
        for(int j=0;j<2;j++){
            float v = cs[nt][j];
            v += __shfl_xor_sync(0xffffffffu, v, 4);
            v += __shfl_xor_sync(0xffffffffu, v, 8);
            v += __shfl_xor_sync(0xffffffffu, v, 16);
            if(lane < 4){
                int c0 = colBase + wn + nt*8 + 2*tq + j;
                atomicAdd(&g_pooled[c0], v);
            }
        }
    }
}

__global__ void __launch_bounds__(256,2) final_gemm_kernel(float* __restrict__ out){
    extern __shared__ char sm[];
    const size_t rowBase = (size_t)blockIdx.y * BM;
    const int colBase = blockIdx.x * BN;
    float acc[4][4][4]; ZERO_ACC(acc);
    auto getA16=[&](int s,int idx){
        int m=idx>>2, c=idx&3;
        int seg=s>>4; int ks=(s&15)*BK + c*8;
        const __half* Ah = seg==0 ? g_xfH : (seg==1 ? g_hud : g_hlr);
        return (const void*)(Ah + (rowBase+m)*DD + ks);
    };
    auto getB16=[&](int s,int idx){
        int p=idx>>5, c=idx&31;
        int seg=s>>4; int gp=(s&15)*16 + p;
        const __half2* Bp = seg==0 ? g_WP : (seg==1 ? g_WudP : g_WlrP);
        return (const void*)(Bp + (size_t)gp*DD + colBase + c*4);
    };
    mainloop_cp(3*DD/BK, acc, sm, getA16, getB16);

    const int lane=threadIdx.x&31, warp=threadIdx.x>>5;
    const int wm=(warp>>2)*64, wn=(warp&3)*32, gq=lane>>2, tq=lane&3;
    #pragma unroll
    for(int mt=0;mt<4;mt++){
        size_t r0 = rowBase + wm + mt*16 + gq;
        #pragma unroll
        for(int nt=0;nt<4;nt++){
            int c0 = colBase + wn + nt*8 + 2*tq;
            float bb0 = g_biasT[c0], bb1 = g_biasT[c0+1];
            float2 v0 = make_float2(fmaxf(acc[mt][nt][0]+bb0,0.f), fmaxf(acc[mt][nt][1]+bb1,0.f));
            float2 v2 = make_float2(fmaxf(acc[mt][nt][2]+bb0,0.f), fmaxf(acc[mt][nt][3]+bb1,0.f));
            *(float2*)(out + r0*DD + c0)     = v0;
            *(float2*)(out + (r0+8)*DD + c0) = v2;
        }
    }
}

// ---------------- launch ----------------
extern "C" void kernel_launch(void* const* d_in, const int* in_sizes, int n_in,
                              void* d_out, int out_size){
    const float* x    = (const float*)d_in[0];
    const float* mask = (const float*)d_in[1];
    const float* a_ud = (const float*)d_in[2];
    const float* a_lr = (const float*)d_in[3];
    const float* W    = (const float*)d_in[4];
    const float* b    = (const float*)d_in[5];
    const float* W_ud = (const float*)d_in[6];
    const float* b_ud = (const float*)d_in[7];
    const float* W_lr = (const float*)d_in[8];
    const float* b_lr = (const float*)d_in[9];
    const float* W_g  = (const float*)d_in[10];
    const float* b_g  = (const float*)d_in[11];
    const float* W_go = (const float*)d_in[12];
    const float* b_go = (const float*)d_in[13];
    float* out = (float*)d_out;

    static bool attr_done = false;
    if(!attr_done){
        cudaFuncSetAttribute(big_gemm_kernel,   cudaFuncAttributeMaxDynamicSharedMemorySize, SMEM_TOTAL);
        cudaFuncSetAttribute(pool_gemm_kernel,  cudaFuncAttributeMaxDynamicSharedMemorySize, SMEM_TOTAL);
        cudaFuncSetAttribute(final_gemm_kernel, cudaFuncAttributeMaxDynamicSharedMemorySize, SMEM_TOTAL);
        attr_done = true;
    }

    wpack_kernel<<<dim3(512,1,4), 256>>>(W, W_ud, W_lr, W_g);
    xfconv_kernel<<<2048, 256>>>(x);
    masksum_kernel<<<1,512>>>(mask);
    pool_gemm_kernel<<<dim3(DD/BN, NROWS/BM), 256, SMEM_TOTAL>>>(b_g, mask);
    gobias_kernel<<<DD/8, 256>>>(W_go, b, b_ud, b_lr, b_go, out + (size_t)NROWS*DD);
    big_gemm_kernel<<<dim3(DD/BN, NROWS/BM, 2), 256, SMEM_TOTAL>>>(a_ud, a_lr);
    final_gemm_kernel<<<dim3(DD/BN, NROWS/BM), 256, SMEM_TOTAL>>>(out);
}

// round 6
// speedup vs baseline: 2.4274x; 1.0710x over previous
#include <cuda_runtime.h>
#include <cuda_fp16.h>
#include <cstdint>

#define NROWS 8192
#define DD    512

#define BM 128
#define BN 128
#define BK 32
#define ASTRIDE 80                 // bytes per A smem row (32 halves + pad); LDSM conflict-free
#define BSTRIDE 544                // bytes per B smem pair-row; conflict-free
#define A_TILE (BM*ASTRIDE)        // 10240
#define B_TILE ((BK/2)*BSTRIDE)    // 8704
#define STAGE  (A_TILE + B_TILE)   // 18944
#define NSTAGE 4
#define SMEM_TOTAL (NSTAGE*STAGE)  // 75776
#define HG_OFF   SMEM_TOTAL
#define SB_OFF   (HG_OFF + DD*4)
#define FINAL_SMEM (SB_OFF + 128*4)

#define HP_SZ ((size_t)NROWS*DD)

// ---------------- device scratch ----------------
__device__ __half  g_xfH[NROWS*DD];          // xf fp16 row-major
__device__ __half2 g_xfP[(NROWS/2)*DD];      // xf k-pair-packed [k/2][n]
__device__ __half  g_hp[4*NROWS*DD];         // partials: [ud.h0, ud.h1, lr.h0, lr.h1]
__device__ float   g_yx[NROWS*DD];           // xf @ W^T fp32
__device__ __half2 g_WP  [(DD/2)*DD];
__device__ __half2 g_WudP[(DD/2)*DD];
__device__ __half2 g_WlrP[(DD/2)*DD];
__device__ __half2 g_WgP [(DD/2)*DD];
__device__ float   g_pooled[DD];
__device__ float   g_nsum;

// ---------------- helpers ----------------
__device__ __forceinline__ uint32_t smem_u32(const void* p){
    return (uint32_t)__cvta_generic_to_shared(p);
}
__device__ __forceinline__ void cpasync16(uint32_t s, const void* g){
    asm volatile("cp.async.cg.shared.global [%0], [%1], 16;\n" :: "r"(s), "l"(g));
}
__device__ __forceinline__ void hmma(float* c, const uint32_t a[4], const uint32_t b[2]){
    asm volatile(
      "mma.sync.aligned.m16n8k16.row.col.f32.f16.f16.f32 "
      "{%0,%1,%2,%3},{%4,%5,%6,%7},{%8,%9},{%0,%1,%2,%3};\n"
      : "+f"(c[0]),"+f"(c[1]),"+f"(c[2]),"+f"(c[3])
      : "r"(a[0]),"r"(a[1]),"r"(a[2]),"r"(a[3]),"r"(b[0]),"r"(b[1]));
}
__device__ __forceinline__ void ldsm4(uint32_t* r, uint32_t addr){
    asm volatile("ldmatrix.sync.aligned.m8n8.x4.shared.b16 {%0,%1,%2,%3}, [%4];"
        : "=r"(r[0]),"=r"(r[1]),"=r"(r[2]),"=r"(r[3]) : "r"(addr));
}
__device__ __forceinline__ uint32_t lds32(uint32_t addr){
    uint32_t v; asm volatile("ld.shared.b32 %0, [%1];" : "=r"(v) : "r"(addr)); return v;
}
__device__ __forceinline__ void sts_u2(uint32_t addr, uint32_t x, uint32_t y){
    asm volatile("st.shared.v2.b32 [%0], {%1,%2};" :: "r"(addr), "r"(x), "r"(y));
}
__device__ __forceinline__ void sts_u4(uint32_t addr, uint4 v){
    asm volatile("st.shared.v4.b32 [%0], {%1,%2,%3,%4};"
        :: "r"(addr), "r"(v.x), "r"(v.y), "r"(v.z), "r"(v.w));
}
__device__ __forceinline__ uint32_t hadd2u(uint32_t a, uint32_t b){
    __half2 r = __hadd2(*(__half2*)&a, *(__half2*)&b); return *(uint32_t*)&r;
}

#define ZERO_ACC(acc) do{ _Pragma("unroll") for(int i_=0;i_<4;i_++) \
    _Pragma("unroll") for(int j_=0;j_<4;j_++) \
    _Pragma("unroll") for(int q_=0;q_<4;q_++) acc[i_][j_][q_]=0.f; }while(0)

// One BK=32 tile of MMAs. A via ldmatrix.x4, B via LDS.32.
__device__ __forceinline__ void compute_tile(uint32_t As, uint32_t Bs,
                                             float (&acc)[4][4][4],
                                             int wm,int wn,int gq,int tq,int lane){
    const uint32_t arow = lane & 15;
    const uint32_t acol = (lane >> 4) * 16;
    const uint32_t abase = As + (wm + arow)*ASTRIDE + acol;
    const uint32_t bbase = Bs + tq*BSTRIDE + (wn + gq)*4;
    #pragma unroll
    for(int kk=0;kk<2;kk++){
        uint32_t a[4][4], b[4][2];
        #pragma unroll
        for(int mt=0;mt<4;mt++)
            ldsm4(a[mt], abase + mt*16*ASTRIDE + kk*32);
        #pragma unroll
        for(int nt=0;nt<4;nt++){
            uint32_t p = bbase + kk*8*BSTRIDE + nt*32;
            b[nt][0] = lds32(p);
            b[nt][1] = lds32(p + 4*BSTRIDE);
        }
        #pragma unroll
        for(int mt=0;mt<4;mt++)
            #pragma unroll
            for(int nt=0;nt<4;nt++)
                hmma(acc[mt][nt], a[mt], b[nt]);
    }
}

// ---- mainloop A: A fp32 global, converted in-flight ----
template<class FA, class FB>
__device__ __forceinline__ void mainloop_conv(int nk, float (&acc)[4][4][4],
                                              char* sm, FA getAf4, FB getB16){
    const int tid = threadIdx.x;
    const uint32_t smb = smem_u32(sm);
    const int lane=tid&31, warp=tid>>5;
    const int wm=(warp>>2)*64, wn=(warp&3)*32, gq=lane>>2, tq=lane&3;

    float4 av[4];
    #pragma unroll
    for(int r=0;r<4;r++) av[r] = __ldg(getAf4(0, tid + r*256));

    #pragma unroll
    for(int pg=0; pg<2; pg++){
        if(pg < nk){
            const uint32_t bb = smb + pg*STAGE + A_TILE;
            #pragma unroll
            for(int r=0;r<2;r++){
                int idx = tid + r*256; int p=idx>>5, c=idx&31;
                cpasync16(bb + p*BSTRIDE + c*16, getB16(pg, idx));
            }
        }
        asm volatile("cp.async.commit_group;" ::: "memory");
    }

    for(int kt=0; kt<nk; ++kt){
        const uint32_t ab = smb + (kt&3)*STAGE;
        #pragma unroll
        for(int r=0;r<4;r++){
            int idx = tid + r*256; int m=idx>>3, c=idx&7;
            __half2 h0 = __floats2half2_rn(av[r].x, av[r].y);
            __half2 h1 = __floats2half2_rn(av[r].z, av[r].w);
            sts_u2(ab + m*ASTRIDE + c*8, *(uint32_t*)&h0, *(uint32_t*)&h1);
        }
        if(kt+1 < nk){
            #pragma unroll
            for(int r=0;r<4;r++) av[r] = __ldg(getAf4(kt+1, tid + r*256));
        }
        if(kt+2 < nk){
            const uint32_t bb = smb + ((kt+2)&3)*STAGE + A_TILE;
            #pragma unroll
            for(int r=0;r<2;r++){
                int idx = tid + r*256; int p=idx>>5, c=idx&31;
                cpasync16(bb + p*BSTRIDE + c*16, getB16(kt+2, idx));
            }
        }
        asm volatile("cp.async.commit_group;" ::: "memory");
        asm volatile("cp.async.wait_group 2;" ::: "memory");
        __syncthreads();
        compute_tile(ab, ab + A_TILE, acc, wm, wn, gq, tq, lane);
    }
}

// ---- mainloop B: both operands via cp.async ----
template<class FA, class FB>
__device__ __forceinline__ void mainloop_cp(int nk, float (&acc)[4][4][4],
                                            char* sm, FA getA16, FB getB16){
    const int tid = threadIdx.x;
    const uint32_t smb = smem_u32(sm);
    const int lane=tid&31, warp=tid>>5;
    const int wm=(warp>>2)*64, wn=(warp&3)*32, gq=lane>>2, tq=lane&3;

    auto stage_loads = [&](int s){
        const uint32_t ab = smb + (s&3)*STAGE;
        const uint32_t bb = ab + A_TILE;
        #pragma unroll
        for(int r=0;r<2;r++){
            int idx = tid + r*256; int m=idx>>2, c=idx&3;
            cpasync16(ab + m*ASTRIDE + c*16, getA16(s, idx));
        }
        #pragma unroll
        for(int r=0;r<2;r++){
            int idx = tid + r*256; int p=idx>>5, c=idx&31;
            cpasync16(bb + p*BSTRIDE + c*16, getB16(s, idx));
        }
    };

    #pragma unroll
    for(int pg=0; pg<2; pg++){
        if(pg < nk) stage_loads(pg);
        asm volatile("cp.async.commit_group;" ::: "memory");
    }
    for(int kt=0; kt<nk; ++kt){
        if(kt+2 < nk) stage_loads(kt+2);
        asm volatile("cp.async.commit_group;" ::: "memory");
        asm volatile("cp.async.wait_group 2;" ::: "memory");
        __syncthreads();
        const uint32_t ab = smb + (kt&3)*STAGE;
        compute_tile(ab, ab + A_TILE, acc, wm, wn, gq, tq, lane);
    }
}

// ---- mainloop C: A = sum of two fp16 sources (LDG + HADD2 + STS), B via cp.async ----
template<class FA0, class FA1, class FB>
__device__ __forceinline__ void mainloop_sum(int nk, float (&acc)[4][4][4],
                                             char* sm, FA0 getA0, FA1 getA1, FB getB16){
    const int tid = threadIdx.x;
    const uint32_t smb = smem_u32(sm);
    const int lane=tid&31, warp=tid>>5;
    const int wm=(warp>>2)*64, wn=(warp&3)*32, gq=lane>>2, tq=lane&3;

    uint4 a0[2], a1[2];
    #pragma unroll
    for(int r=0;r<2;r++){
        a0[r] = __ldg((const uint4*)getA0(0, tid + r*256));
        a1[r] = __ldg((const uint4*)getA1(0, tid + r*256));
    }
    #pragma unroll
    for(int pg=0; pg<2; pg++){
        if(pg < nk){
            const uint32_t bb = smb + pg*STAGE + A_TILE;
            #pragma unroll
            for(int r=0;r<2;r++){
                int idx = tid + r*256; int p=idx>>5, c=idx&31;
                cpasync16(bb + p*BSTRIDE + c*16, getB16(pg, idx));
            }
        }
        asm volatile("cp.async.commit_group;" ::: "memory");
    }
    for(int kt=0; kt<nk; ++kt){
        const uint32_t ab = smb + (kt&3)*STAGE;
        #pragma unroll
        for(int r=0;r<2;r++){
            int idx = tid + r*256; int m=idx>>2, c=idx&3;
            uint4 v;
            v.x = hadd2u(a0[r].x, a1[r].x); v.y = hadd2u(a0[r].y, a1[r].y);
            v.z = hadd2u(a0[r].z, a1[r].z); v.w = hadd2u(a0[r].w, a1[r].w);
            sts_u4(ab + m*ASTRIDE + c*16, v);
        }
        if(kt+1 < nk){
            #pragma unroll
            for(int r=0;r<2;r++){
                a0[r] = __ldg((const uint4*)getA0(kt+1, tid + r*256));
                a1[r] = __ldg((const uint4*)getA1(kt+1, tid + r*256));
            }
        }
        if(kt+2 < nk){
            const uint32_t bb = smb + ((kt+2)&3)*STAGE + A_TILE;
            #pragma unroll
            for(int r=0;r<2;r++){
                int idx = tid + r*256; int p=idx>>5, c=idx&31;
                cpasync16(bb + p*BSTRIDE + c*16, getB16(kt+2, idx));
            }
        }
        asm volatile("cp.async.commit_group;" ::: "memory");
        asm volatile("cp.async.wait_group 2;" ::: "memory");
        __syncthreads();
        compute_tile(ab, ab + A_TILE, acc, wm, wn, gq, tq, lane);
    }
}

// ---------------- prep: xf conversion + weight packing + mask sum ----------------
__global__ void prep_kernel(const float* __restrict__ xf, const float* __restrict__ mask,
                            const float* __restrict__ W,  const float* __restrict__ Wud,
                            const float* __restrict__ Wlr,const float* __restrict__ Wg){
    const int bx = blockIdx.x, tid = threadIdx.x;
    if(bx < 2048){
        int idx = bx*256 + tid;
        int p = idx >> 7, n4 = (idx & 127)*4;
        float4 v0 = *(const float4*)(xf + (size_t)(2*p)*DD + n4);
        float4 v1 = *(const float4*)(xf + (size_t)(2*p+1)*DD + n4);
        __half2 r0 = __floats2half2_rn(v0.x, v0.y), r1 = __floats2half2_rn(v0.z, v0.w);
        __half2 r2 = __floats2half2_rn(v1.x, v1.y), r3 = __floats2half2_rn(v1.z, v1.w);
        uint2 u0; u0.x=*(uint32_t*)&r0; u0.y=*(uint32_t*)&r1;
        uint2 u1; u1.x=*(uint32_t*)&r2; u1.y=*(uint32_t*)&r3;
        *(uint2*)(g_xfH + (size_t)(2*p)*DD + n4)   = u0;
        *(uint2*)(g_xfH + (size_t)(2*p+1)*DD + n4) = u1;
        __half2 p0 = __floats2half2_rn(v0.x, v1.x);
        __half2 p1 = __floats2half2_rn(v0.y, v1.y);
        __half2 p2 = __floats2half2_rn(v0.z, v1.z);
        __half2 p3 = __floats2half2_rn(v0.w, v1.w);
        uint4 up; up.x=*(uint32_t*)&p0; up.y=*(uint32_t*)&p1; up.z=*(uint32_t*)&p2; up.w=*(uint32_t*)&p3;
        *(uint4*)(g_xfP + (size_t)p*DD + n4) = up;
    } else if(bx < 4096){
        int i = bx - 2048;
        const float* src; __half2* dst;
        switch(i >> 9){
            case 0: src=W;   dst=g_WP;   break;
            case 1: src=Wud; dst=g_WudP; break;
            case 2: src=Wlr; dst=g_WlrP; break;
            default:src=Wg;  dst=g_WgP;  break;
        }
        int idx = (i & 511)*256 + tid;
        int p = idx >> 9, n = idx & 511;
        float2 v = *(const float2*)(src + (size_t)n*DD + 2*p);
        dst[(size_t)p*DD + n] = __floats2half2_rn(v.x, v.y);
    } else {
        __shared__ float red[256];
        float s=0.f;
        for(int i=tid;i<NROWS;i+=256) s += mask[i];
        red[tid]=s; __syncthreads();
        for(int st=128;st>0;st>>=1){
            if(tid<st) red[tid]+=red[tid+st];
            __syncthreads();
        }
        if(tid==0) g_nsum = red[0];
        g_pooled[tid]     = 0.f;
        g_pooled[tid+256] = 0.f;
    }
}

// ---------------- mega: big half-K aggregations + pool + y_x ----------------
__global__ void __launch_bounds__(256,2) mega_kernel(
        const float* __restrict__ a_ud, const float* __restrict__ a_lr,
        const float* __restrict__ b_g,  const float* __restrict__ mask){
    extern __shared__ char sm[];
    const int bx = blockIdx.x;
    const int lane=threadIdx.x&31, warp=threadIdx.x>>5;
    const int wm=(warp>>2)*64, wn=(warp&3)*32, gq=lane>>2, tq=lane&3;
    float acc[4][4][4]; ZERO_ACC(acc);

    if(bx < 1024){
        // big aggregation half: mat = bx>>9, half = (bx>>8)&1
        const int mat = bx>>9, half = (bx>>8)&1;
        const int col = (bx>>6)&3, row = bx&63;
        const float* A = mat ? a_lr : a_ud;
        __half* C = g_hp + (size_t)(mat*2 + half)*HP_SZ;
        const size_t rowBase = (size_t)row * BM;
        const int colBase = col * BN;
        const int kOff = half * 4096;
        auto getAf4=[&](int s,int idx){
            int m=idx>>3, c=idx&7;
            return (const float4*)(A + (rowBase+m)*NROWS + kOff + s*BK + c*4);
        };
        auto getB16=[&](int s,int idx){
            int p=idx>>5, c=idx&31;
            return (const void*)(g_xfP + (size_t)(kOff/2 + s*16 + p)*DD + colBase + c*4);
        };
        mainloop_conv(4096/BK, acc, sm, getAf4, getB16);
        #pragma unroll
        for(int mt=0;mt<4;mt++){
            size_t r0 = rowBase + wm + mt*16 + gq;
            #pragma unroll
            for(int nt=0;nt<4;nt++){
                int c0 = colBase + wn + nt*8 + 2*tq;
                *(__half2*)(C + r0*DD + c0)     = __floats2half2_rn(acc[mt][nt][0], acc[mt][nt][1]);
                *(__half2*)(C + (r0+8)*DD + c0) = __floats2half2_rn(acc[mt][nt][2], acc[mt][nt][3]);
            }
        }
    } else if(bx < 1280){
        // pool: pooled[c] += sum_r mask[r]*relu((xf@Wg^T)[r,c] + b_g[c])
        const int i = bx - 1024;
        const size_t rowBase = (size_t)(i & 63) * BM;
        const int colBase = (i >> 6) * BN;
        auto getA16=[&](int s,int idx){
            int m=idx>>2, c=idx&3;
            return (const void*)(g_xfH + (rowBase+m)*DD + s*BK + c*8);
        };
        auto getB16=[&](int s,int idx){
            int p=idx>>5, c=idx&31;
            return (const void*)(g_WgP + (size_t)(s*16+p)*DD + colBase + c*4);
        };
        mainloop_cp(DD/BK, acc, sm, getA16, getB16);
        float cs[4][2];
        #pragma unroll
        for(int nt=0;nt<4;nt++){ cs[nt][0]=0.f; cs[nt][1]=0.f; }
        #pragma unroll
        for(int mt=0;mt<4;mt++){
            size_t r0 = rowBase + wm + mt*16 + gq;
            float m0 = mask[r0], m8 = mask[r0+8];
            #pragma unroll
            for(int nt=0;nt<4;nt++){
                int c0 = colBase + wn + nt*8 + 2*tq;
                float bg0 = b_g[c0], bg1 = b_g[c0+1];
                cs[nt][0] += fmaxf(acc[mt][nt][0]+bg0,0.f)*m0 + fmaxf(acc[mt][nt][2]+bg0,0.f)*m8;
                cs[nt][1] += fmaxf(acc[mt][nt][1]+bg1,0.f)*m0 + fmaxf(acc[mt][nt][3]+bg1,0.f)*m8;
            }
        }
        #pragma unroll
        for(int nt=0;nt<4;nt++){
            #pragma unroll
            for(int j=0;j<2;j++){
                float v = cs[nt][j];
                v += __shfl_xor_sync(0xffffffffu, v, 4);
                v += __shfl_xor_sync(0xffffffffu, v, 8);
                v += __shfl_xor_sync(0xffffffffu, v, 16);
                if(lane < 4)
                    atomicAdd(&g_pooled[colBase + wn + nt*8 + 2*tq + j], v);
            }
        }
    } else {
        // y_x = xf @ W^T (fp32 out, no bias)
        const int i = bx - 1280;
        const size_t rowBase = (size_t)(i & 63) * BM;
        const int colBase = (i >> 6) * BN;
        auto getA16=[&](int s,int idx){
            int m=idx>>2, c=idx&3;
            return (const void*)(g_xfH + (rowBase+m)*DD + s*BK + c*8);
        };
        auto getB16=[&](int s,int idx){
            int p=idx>>5, c=idx&31;
            return (const void*)(g_WP + (size_t)(s*16+p)*DD + colBase + c*4);
        };
        mainloop_cp(DD/BK, acc, sm, getA16, getB16);
        #pragma unroll
        for(int mt=0;mt<4;mt++){
            size_t r0 = rowBase + wm + mt*16 + gq;
            #pragma unroll
            for(int nt=0;nt<4;nt++){
                int c0 = colBase + wn + nt*8 + 2*tq;
                *(float2*)(g_yx + r0*DD + c0)     = make_float2(acc[mt][nt][0], acc[mt][nt][1]);
                *(float2*)(g_yx + (r0+8)*DD + c0) = make_float2(acc[mt][nt][2], acc[mt][nt][3]);
            }
        }
    }
}

// ---------------- final: h = relu( y_x + (h_ud)@Wud^T + (h_lr)@Wlr^T + bias ) ----------------
__global__ void __launch_bounds__(256,2) final_kernel(
        const float* __restrict__ W_go,
        const float* __restrict__ b,   const float* __restrict__ b_ud,
        const float* __restrict__ b_lr,const float* __restrict__ b_go,
        float* __restrict__ out){
    extern __shared__ char sm[];
    float* hg    = (float*)(sm + HG_OFF);
    float* sbias = (float*)(sm + SB_OFF);
    const int tid = threadIdx.x;
    const size_t rowBase = (size_t)(blockIdx.x & 63) * BM;
    const int colBase = (blockIdx.x >> 6) * BN;

    // hg = pooled / n
    {
        float inv = 1.0f / g_nsum;
        hg[tid]     = g_pooled[tid]*inv;
        hg[tid+256] = g_pooled[tid+256]*inv;
    }
    __syncthreads();
    if(blockIdx.x == 0){
        out[HP_SZ + tid]       = hg[tid];
        out[HP_SZ + tid + 256] = hg[tid+256];
    }
    // per-column bias: b + b_ud + b_lr + b_go + hg @ W_go^T (2 threads per column)
    {
        int j = colBase + (tid>>1);
        int k0 = (tid&1)*256;
        const float4* wr = (const float4*)(W_go + (size_t)j*DD + k0);
        float s = 0.f;
        #pragma unroll 8
        for(int q=0;q<64;q++){
            float4 wv = wr[q];
            s += hg[k0+4*q]*wv.x + hg[k0+4*q+1]*wv.y + hg[k0+4*q+2]*wv.z + hg[k0+4*q+3]*wv.w;
        }
        s += __shfl_xor_sync(0xffffffffu, s, 1);
        if((tid&1)==0) sbias[tid>>1] = s + b[j] + b_ud[j] + b_lr[j] + b_go[j];
    }
    __syncthreads();

    float acc[4][4][4]; ZERO_ACC(acc);
    // K=1024: seg 0 = h_ud (partials 0+1), seg 1 = h_lr (partials 2+3)
    auto getA0=[&](int s,int idx){
        int m=idx>>2, c=idx&3; int seg=s>>4;
        const __half* A = g_hp + (size_t)(seg*2)*HP_SZ;
        return (const void*)(A + (rowBase+m)*DD + (s&15)*BK + c*8);
    };
    auto getA1=[&](int s,int idx){
        int m=idx>>2, c=idx&3; int seg=s>>4;
        const __half* A = g_hp + (size_t)(seg*2+1)*HP_SZ;
        return (const void*)(A + (rowBase+m)*DD + (s&15)*BK + c*8);
    };
    auto getB16=[&](int s,int idx){
        int p=idx>>5, c=idx&31; int seg=s>>4;
        const __half2* B = seg ? g_WlrP : g_WudP;
        return (const void*)(B + (size_t)((s&15)*16+p)*DD + colBase + c*4);
    };
    mainloop_sum(2*DD/BK, acc, sm, getA0, getA1, getB16);

    const int lane=tid&31, warp=tid>>5;
    const int wm=(warp>>2)*64, wn=(warp&3)*32, gq=lane>>2, tq=lane&3;
    #pragma unroll
    for(int mt=0;mt<4;mt++){
        size_t r0 = rowBase + wm + mt*16 + gq;
        #pragma unroll
        for(int nt=0;nt<4;nt++){
            int c0 = colBase + wn + nt*8 + 2*tq;
            float bb0 = sbias[c0-colBase], bb1 = sbias[c0-colBase+1];
            float2 y0 = *(const float2*)(g_yx + r0*DD + c0);
            float2 y2 = *(const float2*)(g_yx + (r0+8)*DD + c0);
            float2 v0 = make_float2(fmaxf(acc[mt][nt][0]+y0.x+bb0,0.f),
                                    fmaxf(acc[mt][nt][1]+y0.y+bb1,0.f));
            float2 v2 = make_float2(fmaxf(acc[mt][nt][2]+y2.x+bb0,0.f),
                                    fmaxf(acc[mt][nt][3]+y2.y+bb1,0.f));
            *(float2*)(out + r0*DD + c0)     = v0;
            *(float2*)(out + (r0+8)*DD + c0) = v2;
        }
    }
}

// ---------------- launch ----------------
extern "C" void kernel_launch(void* const* d_in, const int* in_sizes, int n_in,
                              void* d_out, int out_size){
    const float* x    = (const float*)d_in[0];
    const float* mask = (const float*)d_in[1];
    const float* a_ud = (const float*)d_in[2];
    const float* a_lr = (const float*)d_in[3];
    const float* W    = (const float*)d_in[4];
    const float* b    = (const float*)d_in[5];
    const float* W_ud = (const float*)d_in[6];
    const float* b_ud = (const float*)d_in[7];
    const float* W_lr = (const float*)d_in[8];
    const float* b_lr = (const float*)d_in[9];
    const float* W_g  = (const float*)d_in[10];
    const float* b_g  = (const float*)d_in[11];
    const float* W_go = (const float*)d_in[12];
    const float* b_go = (const float*)d_in[13];
    float* out = (float*)d_out;

    static bool attr_done = false;
    if(!attr_done){
        cudaFuncSetAttribute(mega_kernel,  cudaFuncAttributeMaxDynamicSharedMemorySize, SMEM_TOTAL);
        cudaFuncSetAttribute(final_kernel, cudaFuncAttributeMaxDynamicSharedMemorySize, FINAL_SMEM);
        attr_done = true;
    }

    prep_kernel<<<4097, 256>>>(x, mask, W, W_ud, W_lr, W_g);
    mega_kernel<<<1536, 256, SMEM_TOTAL>>>(a_ud, a_lr, b_g, mask);
    final_kernel<<<256, 256, FINAL_SMEM>>>(W_go, b, b_ud, b_lr, b_go, out);
}